// round 9
// baseline (speedup 1.0000x reference)
#include <cuda_runtime.h>
#include <cstdint>

#define B_      16
#define NCLS_   3
#define CREG_   50
#define H_      96
#define W_      320
#define HW_     (H_*W_)          // 30720
#define K_      100
#define NBIN_   320
#define BIN_CAP 1024
#define SURV_   2048
#define NOUT_   13
#define THRESH_ 0.2f
#define EPS_    1e-6f
#define RAW_PRE (-1.39f)
#define MARGIN_ (0.01f)
#define TILE_Y  16
#define NTB     (H_/TILE_Y)      // 6 stripes
#define NT_     512

static __device__ unsigned long long g_cand2[B_][NBIN_][BIN_CAP];  // bucketed by score bin
static __device__ int                g_hist[B_][NT_];              // zero-init; re-zeroed by k_selfin

__device__ __forceinline__ float sigf(float x) { return 1.0f / (1.0f + expf(-x)); }

// ---------------- tiled NMS + bucketed candidate scatter ----------------
__global__ void __launch_bounds__(W_) k_nms(const float* __restrict__ hmp) {
    __shared__ float tile[TILE_Y+2][W_];

    int blk = blockIdx.x;
    int bc  = blk / NTB;             // b*NCLS + c
    int t   = blk % NTB;
    int b   = bc / NCLS_;
    int c   = bc % NCLS_;
    int y0  = t * TILE_Y;
    int x   = threadIdx.x;           // 0..319

    const float* base = hmp + (size_t)bc * HW_;
    #pragma unroll
    for (int r = 0; r < TILE_Y+2; ++r) {
        int gy = y0 + r - 1;
        tile[r][x] = (gy >= 0 && gy < H_) ? __ldg(&base[gy*W_ + x]) : -3.0e38f;
    }
    __syncthreads();

    bool lf = (x > 0), rt = (x < W_-1);
    #pragma unroll
    for (int ly = 0; ly < TILE_Y; ++ly) {
        float raw = tile[ly+1][x];
        if (raw < RAW_PRE) continue;
        float m = fmaxf(tile[ly][x], tile[ly+2][x]);
        if (lf) m = fmaxf(m, fmaxf(tile[ly][x-1], fmaxf(tile[ly+1][x-1], tile[ly+2][x-1])));
        if (rt) m = fmaxf(m, fmaxf(tile[ly][x+1], fmaxf(tile[ly+1][x+1], tile[ly+2][x+1])));
        if (raw < m) {
            if (m - raw >= MARGIN_ && raw < 8.0f) continue;   // safe raw-space reject
            if (sigf(m) > sigf(raw)) continue;                // exact sigmoid-space tie check
        }
        float s = sigf(raw);                                  // exact reference sigmoid
        if (!(s >= THRESH_)) continue;
        int ind = (y0 + ly)*W_ + x;
        unsigned lo = 0xFFFFFFFFu - (unsigned)(c*HW_ + ind);
        unsigned long long key = ((unsigned long long)__float_as_uint(s) << 32) | lo;
        int bin = (int)(unsigned)(key >> 48) - 0x3E4C;        // scores in [0.2,1] -> [0,308]
        bin = max(0, min(NBIN_-1, bin));
        int pos = atomicAdd(&g_hist[b][bin], 1);
        if (pos < BIN_CAP) g_cand2[b][bin][pos] = key;
    }
}

// ---------------- fused top-100 select + final math, one block per batch ----------------
__constant__ int c_chan[24] = {0,1,2,3,4,5,6,7,8,
                               26,28,30,32,34,36,38,40,42,44,
                               45,46,47,48,49};

__global__ void __launch_bounds__(NT_) k_selfin(
        const float* __restrict__ pred_reg,
        const float* __restrict__ calib,
        const float* __restrict__ pad_size,
        const float* __restrict__ dim_mean,
        float* __restrict__ out) {
    const int b    = blockIdx.x;
    const int tid  = threadIdx.x;            // 0..511 (thread == bin)
    const int lane = tid & 31, w = tid >> 5;
    __shared__ int S[NT_];                   // clamped-count suffix sums
    __shared__ int wtot[16];
    __shared__ unsigned long long surv[SURV_];
    __shared__ unsigned long long sorted[K_];
    __shared__ float gv[K_][24];
    __shared__ int s_bstar;

    // capture + reset histogram (registers first, barrier, then reset)
    int hv = min(g_hist[b][tid], BIN_CAP);
    __syncthreads();
    g_hist[b][tid] = 0;

    // warp-shuffle suffix scan over 512 bins
    int val = hv;
    #pragma unroll
    for (int off = 1; off < 32; off <<= 1) {
        int tv = __shfl_down_sync(0xFFFFFFFFu, val, off);
        if (lane + off < 32) val += tv;
    }
    if (lane == 0) wtot[w] = val;
    __syncthreads();
    if (w == 0) {
        int tv = (lane < 16) ? wtot[lane] : 0;
        #pragma unroll
        for (int off = 1; off < 16; off <<= 1) {
            int t2 = __shfl_down_sync(0xFFFFFFFFu, tv, off);
            if (lane + off < 16) tv += t2;
        }
        if (lane < 16) wtot[lane] = tv;
    }
    __syncthreads();
    S[tid] = val + ((w + 1 < 16) ? wtot[w + 1] : 0);
    __syncthreads();

    int n = S[0];
    int target = n < K_ ? n : K_;

    if (target > 0) {
        {
            int nxt = (tid < NT_-1) ? S[tid + 1] : 0;
            if (S[tid] >= target && nxt < target) s_bstar = tid;
        }
        __syncthreads();
        const int bstar = s_bstar;
        const int sc = min(S[bstar], SURV_);

        // copy only bins >= bstar into surv (one thread per bin)
        if (tid >= bstar && tid < NBIN_ && hv > 0) {
            int dst = S[bstar] - S[tid];     // items in bins [bstar, tid)
            for (int j = 0; j < hv; ++j) {
                int p = dst + j;
                if (p < SURV_) surv[p] = g_cand2[b][tid][j];
            }
        }
        __syncthreads();

        // rank-by-counting sort (keys unique); exact reference tie order
        for (int i = tid; i < sc; i += NT_) {
            unsigned long long ki = surv[i];
            int r = 0;
            for (int j = 0; j < sc; ++j) r += (surv[j] > ki);
            if (r < K_) sorted[r] = ki;
        }
        __syncthreads();

        // gather 24 channels per selected detection (latency-parallel)
        const float* rbase = pred_reg + (size_t)b * CREG_ * HW_;
        for (int i = tid; i < target * 24; i += NT_) {
            int d  = i / 24;
            int ch = i % 24;
            unsigned lo = 0xFFFFFFFFu - (unsigned)(sorted[d] & 0xFFFFFFFFu);
            int ind = (int)(lo % HW_);
            gv[d][ch] = __ldg(&rbase[c_chan[ch] * HW_ + ind]);
        }
        __syncthreads();
    }

    if (tid >= K_) return;
    float* row = out + (size_t)(b*K_ + tid) * NOUT_;
    if (tid >= target) {
        #pragma unroll
        for (int j = 0; j < NOUT_; ++j) row[j] = 0.0f;
        return;
    }

    unsigned long long key = sorted[tid];
    float score = __uint_as_float((unsigned)(key >> 32));
    unsigned lo = 0xFFFFFFFFu - (unsigned)(key & 0xFFFFFFFFu);
    int cls = (int)(lo / HW_);
    int ind = (int)(lo % HW_);
    float fx = (float)(ind % W_);
    float fy = (float)(ind / W_);
    const float* v = gv[tid];

    float fu = calib[b*4+0], cu = calib[b*4+1], fv = calib[b*4+2], cv = calib[b*4+3];
    float pw = pad_size[b*2+0], ph = pad_size[b*2+1];

    float r0 = fmaxf(v[0], 0.f), r1 = fmaxf(v[1], 0.f);
    float r2 = fmaxf(v[2], 0.f), r3 = fmaxf(v[3], 0.f);
    const float HIX = (float)(W_*4 - 1), HIY = (float)(H_*4 - 1);
    float bx0 = fminf(fmaxf((fx - r0)*4.f - pw, 0.f), HIX);
    float by0 = fminf(fmaxf((fy - r1)*4.f - ph, 0.f), HIY);
    float bx1 = fminf(fmaxf((fx + r2)*4.f - pw, 0.f), HIX);
    float by1 = fminf(fmaxf((fy + r3)*4.f - ph, 0.f), HIY);

    const float* dm = dim_mean + cls*3;
    float d0 = expf(v[6]) * dm[0];
    float d1 = expf(v[7]) * dm[1];
    float d2 = expf(v[8]) * dm[2];
    float h3d = d1;

    float fh = fu * h3d;
    float d_ctr = fh / (fmaxf(v[17] - v[18], 0.f)*4.f + EPS_);
    float d_02  = 0.5f * (fh / (fmaxf(v[9]  - v[13], 0.f)*4.f + EPS_)
                        + fh / (fmaxf(v[11] - v[15], 0.f)*4.f + EPS_));
    float d_13  = 0.5f * (fh / (fmaxf(v[10] - v[14], 0.f)*4.f + EPS_)
                        + fh / (fmaxf(v[12] - v[16], 0.f)*4.f + EPS_));
    float kd0 = fminf(fmaxf(d_ctr, 0.1f), 100.f);
    float kd1 = fminf(fmaxf(d_02 , 0.1f), 100.f);
    float kd2 = fminf(fmaxf(d_13 , 0.1f), 100.f);

    float doff   = v[22];
    float sgd    = 1.0f / (1.0f + expf(-doff));
    float direct = fminf(fmaxf(1.0f / sgd - 1.0f, 0.1f), 100.f);

    float u0 = expf(v[23]);
    float u1 = expf(v[19]);
    float u2 = expf(v[20]);
    float u3 = expf(v[21]);
    float w0 = 1.f/u0, w1 = 1.f/u1, w2 = 1.f/u2, w3 = 1.f/u3;
    float Sw = w0 + w1 + w2 + w3;
    w0 /= Sw; w1 /= Sw; w2 /= Sw; w3 /= Sw;
    float depth = direct*w0 + kd0*w1 + kd1*w2 + kd2*w3;
    float derr  = w0*u0 + w1*u1 + w2*u2 + w3*u3;

    float projx = (fx + v[4])*4.f - pw;
    float projy = (fy + v[5])*4.f - ph;
    float x3 = (projx - cu) * depth / fu;
    float y3 = (projy - cv) * depth / fv;

    row[0]  = (float)cls;
    row[1]  = score;
    row[2]  = bx0;  row[3]  = by0;  row[4]  = bx1;  row[5]  = by1;
    row[6]  = d0;   row[7]  = d1;   row[8]  = d2;
    row[9]  = x3;   row[10] = y3;   row[11] = depth;
    row[12] = derr;
}

extern "C" void kernel_launch(void* const* d_in, const int* in_sizes, int n_in,
                              void* d_out, int out_size) {
    const float* pred_hmp = (const float*)d_in[0];
    const float* pred_reg = (const float*)d_in[1];
    const float* calib    = (const float*)d_in[2];
    const float* pad_size = (const float*)d_in[3];
    const float* dim_mean = (const float*)d_in[4];
    float* out = (float*)d_out;

    k_nms<<<B_*NCLS_*NTB, W_>>>(pred_hmp);
    k_selfin<<<B_, NT_>>>(pred_reg, calib, pad_size, dim_mean, out);
}

// round 10
// speedup vs baseline: 1.0863x; 1.0863x over previous
#include <cuda_runtime.h>
#include <cstdint>

#define B_      16
#define NCLS_   3
#define CREG_   50
#define H_      96
#define W_      320
#define HW_     (H_*W_)          // 30720
#define K_      100
#define CAP_    24576
#define SURV_   2048
#define NOUT_   13
#define THRESH_ 0.2f
#define EPS_    1e-6f
#define RAW_PRE (-1.39f)
#define MARGIN_ (0.01f)
#define TILE_Y  16
#define NTB     (H_/TILE_Y)      // 6 stripes
#define LBUF_   1024
#define NT_     512

static __device__ unsigned long long g_cand[B_][CAP_];
static __device__ int                g_cnt[B_];        // zero-init; re-zeroed by k_selfin
static __device__ int                g_hist[B_][NT_];  // zero-init; re-zeroed by k_selfin

__device__ __forceinline__ float sigf(float x) { return 1.0f / (1.0f + expf(-x)); }

// ---------------- tiled NMS + lbuf append + smem-hist flush via REDs ----------------
__global__ void __launch_bounds__(W_) k_nms(const float* __restrict__ hmp) {
    __shared__ float tile[TILE_Y+2][W_];
    __shared__ unsigned long long lbuf[LBUF_];
    __shared__ int shist[NT_];
    __shared__ int lcnt, gbase;

    int blk = blockIdx.x;
    int bc  = blk / NTB;             // b*NCLS + c
    int t   = blk % NTB;
    int b   = bc / NCLS_;
    int c   = bc % NCLS_;
    int y0  = t * TILE_Y;
    int x   = threadIdx.x;           // 0..319

    const float* base = hmp + (size_t)bc * HW_;
    #pragma unroll
    for (int r = 0; r < TILE_Y+2; ++r) {
        int gy = y0 + r - 1;
        tile[r][x] = (gy >= 0 && gy < H_) ? __ldg(&base[gy*W_ + x]) : -3.0e38f;
    }
    for (int i = x; i < NT_; i += W_) shist[i] = 0;
    if (x == 0) lcnt = 0;
    __syncthreads();

    bool lf = (x > 0), rt = (x < W_-1);
    #pragma unroll
    for (int ly = 0; ly < TILE_Y; ++ly) {
        float raw = tile[ly+1][x];
        if (raw < RAW_PRE) continue;
        float m = fmaxf(tile[ly][x], tile[ly+2][x]);
        if (lf) m = fmaxf(m, fmaxf(tile[ly][x-1], fmaxf(tile[ly+1][x-1], tile[ly+2][x-1])));
        if (rt) m = fmaxf(m, fmaxf(tile[ly][x+1], fmaxf(tile[ly+1][x+1], tile[ly+2][x+1])));
        if (raw < m) {
            if (m - raw >= MARGIN_ && raw < 8.0f) continue;   // safe raw-space reject
            if (sigf(m) > sigf(raw)) continue;                // exact sigmoid-space tie check
        }
        float s = sigf(raw);                                  // exact reference sigmoid
        if (!(s >= THRESH_)) continue;
        int ind = (y0 + ly)*W_ + x;
        unsigned lo = 0xFFFFFFFFu - (unsigned)(c*HW_ + ind);
        unsigned long long key = ((unsigned long long)__float_as_uint(s) << 32) | lo;
        int bin = (int)(unsigned)(key >> 48) - 0x3E4C;
        bin = max(0, min(NT_-1, bin));
        atomicAdd(&shist[bin], 1);                            // smem, low contention
        int p = atomicAdd(&lcnt, 1);
        if (p < LBUF_) lbuf[p] = key;
        else {
            int gp = atomicAdd(&g_cnt[b], 1);
            if (gp < CAP_) g_cand[b][gp] = key;
        }
    }
    __syncthreads();
    int n = min(lcnt, LBUF_);
    if (x == 0) gbase = atomicAdd(&g_cnt[b], n);
    __syncthreads();
    int gb = gbase;
    for (int i = x; i < n; i += W_) {
        int gp = gb + i;
        if (gp < CAP_) g_cand[b][gp] = lbuf[i];
    }
    // fire-and-forget histogram flush (no return dependency -> REDG)
    for (int i = x; i < NT_; i += W_) {
        int v = shist[i];
        if (v) atomicAdd(&g_hist[b][i], v);
    }
}

// ---------------- fused top-100 select + final math, one block per batch ----------------
__constant__ int c_chan[24] = {0,1,2,3,4,5,6,7,8,
                               26,28,30,32,34,36,38,40,42,44,
                               45,46,47,48,49};

__global__ void __launch_bounds__(NT_) k_selfin(
        const float* __restrict__ pred_reg,
        const float* __restrict__ calib,
        const float* __restrict__ pad_size,
        const float* __restrict__ dim_mean,
        float* __restrict__ out) {
    const int b    = blockIdx.x;
    const int tid  = threadIdx.x;            // 0..511 (thread == bin)
    const int lane = tid & 31, w = tid >> 5;
    __shared__ int S[NT_];
    __shared__ int wtot[16];
    __shared__ int SS[256];
    __shared__ unsigned long long surv[SURV_];
    __shared__ unsigned long long sorted[K_];
    __shared__ float gv[K_][24];
    __shared__ int s_bstar, s_b2, s_scount;

    // capture state, barrier, then reset (no read/write race)
    int n  = g_cnt[b];
    int hv = g_hist[b][tid];
    __syncthreads();
    if (tid == 0) { g_cnt[b] = 0; s_scount = 0; }
    g_hist[b][tid] = 0;

    if (n > CAP_) n = CAP_;
    int target = n < K_ ? n : K_;

    if (n > 0) {
        // warp-shuffle suffix scan over 512 bins
        int val = hv;
        #pragma unroll
        for (int off = 1; off < 32; off <<= 1) {
            int tv = __shfl_down_sync(0xFFFFFFFFu, val, off);
            if (lane + off < 32) val += tv;
        }
        if (lane == 0) wtot[w] = val;
        __syncthreads();
        if (w == 0) {
            int tv = (lane < 16) ? wtot[lane] : 0;
            #pragma unroll
            for (int off = 1; off < 16; off <<= 1) {
                int t2 = __shfl_down_sync(0xFFFFFFFFu, tv, off);
                if (lane + off < 16) tv += t2;
            }
            if (lane < 16) wtot[lane] = tv;
        }
        __syncthreads();
        S[tid] = val + ((w + 1 < 16) ? wtot[w + 1] : 0);
        __syncthreads();
        {
            int nxt = (tid < NT_-1) ? S[tid + 1] : 0;
            if (S[tid] >= target && nxt < target) s_bstar = tid;
        }
        __syncthreads();
        const int bstar = s_bstar;

        if (S[bstar] <= SURV_) {
            // single strided collect pass; smem atomic touched only by accepted keys
            for (int i = tid; i < n; i += NT_) {
                unsigned long long key = g_cand[b][i];
                int bin = (int)(unsigned)(key >> 48) - 0x3E4C;
                bin = max(0, min(NT_-1, bin));
                if (bin >= bstar) {
                    int p = atomicAdd(&s_scount, 1);
                    if (p < SURV_) surv[p] = key;
                }
            }
        } else {
            // rare fat-bin path: 8-bit refinement
            const int m = max(1, target - ((bstar + 1 < NT_) ? S[bstar + 1] : 0));
            if (tid < 256) SS[tid] = 0;
            __syncthreads();
            for (int i = tid; i < n; i += NT_) {
                unsigned long long key = g_cand[b][i];
                int bin = (int)(unsigned)(key >> 48) - 0x3E4C;
                bin = max(0, min(NT_-1, bin));
                if (bin == bstar) atomicAdd(&SS[(unsigned)(key >> 40) & 0xFF], 1);
            }
            __syncthreads();
            if (tid == 0) {
                int acc = 0, b2 = 0;
                for (int s = 255; s >= 0; --s) { acc += SS[s]; if (acc >= m) { b2 = s; break; } }
                s_b2 = b2;
            }
            __syncthreads();
            const int b2 = s_b2;
            for (int i = tid; i < n; i += NT_) {
                unsigned long long key = g_cand[b][i];
                int bin = (int)(unsigned)(key >> 48) - 0x3E4C;
                bin = max(0, min(NT_-1, bin));
                bool take = (bin > bstar) || (bin == bstar && (int)((key >> 40) & 0xFF) >= b2);
                if (take) {
                    int p = atomicAdd(&s_scount, 1);
                    if (p < SURV_) surv[p] = key;
                }
            }
        }
        __syncthreads();
        const int sc = min(s_scount, SURV_);

        // rank-by-counting (keys unique): exact descending reference order, no barriers
        for (int i = tid; i < sc; i += NT_) {
            unsigned long long ki = surv[i];
            int r = 0;
            for (int j = 0; j < sc; ++j) r += (surv[j] > ki);
            if (r < K_) sorted[r] = ki;
        }
        __syncthreads();

        // gather 24 channels per selected detection (latency-parallel)
        const float* rbase = pred_reg + (size_t)b * CREG_ * HW_;
        for (int i = tid; i < target * 24; i += NT_) {
            int d  = i / 24;
            int ch = i % 24;
            unsigned lo = 0xFFFFFFFFu - (unsigned)(sorted[d] & 0xFFFFFFFFu);
            int ind = (int)(lo % HW_);
            gv[d][ch] = __ldg(&rbase[c_chan[ch] * HW_ + ind]);
        }
        __syncthreads();
    }

    if (tid >= K_) return;
    float* row = out + (size_t)(b*K_ + tid) * NOUT_;
    if (tid >= target) {
        #pragma unroll
        for (int j = 0; j < NOUT_; ++j) row[j] = 0.0f;
        return;
    }

    unsigned long long key = sorted[tid];
    float score = __uint_as_float((unsigned)(key >> 32));
    unsigned lo = 0xFFFFFFFFu - (unsigned)(key & 0xFFFFFFFFu);
    int cls = (int)(lo / HW_);
    int ind = (int)(lo % HW_);
    float fx = (float)(ind % W_);
    float fy = (float)(ind / W_);
    const float* v = gv[tid];

    float fu = calib[b*4+0], cu = calib[b*4+1], fv = calib[b*4+2], cv = calib[b*4+3];
    float pw = pad_size[b*2+0], ph = pad_size[b*2+1];

    float r0 = fmaxf(v[0], 0.f), r1 = fmaxf(v[1], 0.f);
    float r2 = fmaxf(v[2], 0.f), r3 = fmaxf(v[3], 0.f);
    const float HIX = (float)(W_*4 - 1), HIY = (float)(H_*4 - 1);
    float bx0 = fminf(fmaxf((fx - r0)*4.f - pw, 0.f), HIX);
    float by0 = fminf(fmaxf((fy - r1)*4.f - ph, 0.f), HIY);
    float bx1 = fminf(fmaxf((fx + r2)*4.f - pw, 0.f), HIX);
    float by1 = fminf(fmaxf((fy + r3)*4.f - ph, 0.f), HIY);

    const float* dm = dim_mean + cls*3;
    float d0 = expf(v[6]) * dm[0];
    float d1 = expf(v[7]) * dm[1];
    float d2 = expf(v[8]) * dm[2];
    float h3d = d1;

    float fh = fu * h3d;
    float d_ctr = fh / (fmaxf(v[17] - v[18], 0.f)*4.f + EPS_);
    float d_02  = 0.5f * (fh / (fmaxf(v[9]  - v[13], 0.f)*4.f + EPS_)
                        + fh / (fmaxf(v[11] - v[15], 0.f)*4.f + EPS_));
    float d_13  = 0.5f * (fh / (fmaxf(v[10] - v[14], 0.f)*4.f + EPS_)
                        + fh / (fmaxf(v[12] - v[16], 0.f)*4.f + EPS_));
    float kd0 = fminf(fmaxf(d_ctr, 0.1f), 100.f);
    float kd1 = fminf(fmaxf(d_02 , 0.1f), 100.f);
    float kd2 = fminf(fmaxf(d_13 , 0.1f), 100.f);

    float doff   = v[22];
    float sgd    = 1.0f / (1.0f + expf(-doff));
    float direct = fminf(fmaxf(1.0f / sgd - 1.0f, 0.1f), 100.f);

    float u0 = expf(v[23]);
    float u1 = expf(v[19]);
    float u2 = expf(v[20]);
    float u3 = expf(v[21]);
    float w0 = 1.f/u0, w1 = 1.f/u1, w2 = 1.f/u2, w3 = 1.f/u3;
    float Sw = w0 + w1 + w2 + w3;
    w0 /= Sw; w1 /= Sw; w2 /= Sw; w3 /= Sw;
    float depth = direct*w0 + kd0*w1 + kd1*w2 + kd2*w3;
    float derr  = w0*u0 + w1*u1 + w2*u2 + w3*u3;

    float projx = (fx + v[4])*4.f - pw;
    float projy = (fy + v[5])*4.f - ph;
    float x3 = (projx - cu) * depth / fu;
    float y3 = (projy - cv) * depth / fv;

    row[0]  = (float)cls;
    row[1]  = score;
    row[2]  = bx0;  row[3]  = by0;  row[4]  = bx1;  row[5]  = by1;
    row[6]  = d0;   row[7]  = d1;   row[8]  = d2;
    row[9]  = x3;   row[10] = y3;   row[11] = depth;
    row[12] = derr;
}

extern "C" void kernel_launch(void* const* d_in, const int* in_sizes, int n_in,
                              void* d_out, int out_size) {
    const float* pred_hmp = (const float*)d_in[0];
    const float* pred_reg = (const float*)d_in[1];
    const float* calib    = (const float*)d_in[2];
    const float* pad_size = (const float*)d_in[3];
    const float* dim_mean = (const float*)d_in[4];
    float* out = (float*)d_out;

    k_nms<<<B_*NCLS_*NTB, W_>>>(pred_hmp);
    k_selfin<<<B_, NT_>>>(pred_reg, calib, pad_size, dim_mean, out);
}

// round 11
// speedup vs baseline: 1.1742x; 1.0809x over previous
#include <cuda_runtime.h>
#include <cstdint>

#define B_      16
#define NCLS_   3
#define CREG_   50
#define H_      96
#define W_      320
#define HW_     (H_*W_)          // 30720
#define K_      100
#define NBIN_   320
#define BIN_CAP 512
#define SURV_   1024             // >= K_ + BIN_CAP  (provably enough)
#define NOUT_   13
#define THRESH_ 0.2f
#define EPS_    1e-6f
#define RAW_PRE (-1.39f)
#define MARGIN_ (0.01f)
#define TILE_Y  16
#define NTB     (H_/TILE_Y)      // 6 stripes
#define LBUF_   2048
#define NT_     512

static __device__ unsigned long long g_cand2[B_][NBIN_][BIN_CAP]; // bucketed by score bin
static __device__ int                g_hist[B_][NT_];             // zero-init; re-zeroed by k_selfin

__device__ __forceinline__ float sigf(float x) { return 1.0f / (1.0f + expf(-x)); }

__device__ __forceinline__ int key_bin(unsigned long long key) {
    int bin = (int)(unsigned)(key >> 48) - 0x3E4C;   // scores [0.2,1] -> [0,308]
    return max(0, min(NBIN_-1, bin));
}

// ---------------- tiled NMS + smem buffer + block-aggregated bucketed flush ----------------
__global__ void __launch_bounds__(W_) k_nms(const float* __restrict__ hmp) {
    __shared__ float tile[TILE_Y+2][W_];
    __shared__ unsigned long long lbuf[LBUF_];
    __shared__ int shist[NBIN_];     // per-block bin counts
    __shared__ int gpos [NBIN_];     // reserved global base per bin
    __shared__ int scur [NBIN_];     // per-bin cursor for rebin pass
    __shared__ int lcnt;

    int blk = blockIdx.x;
    int bc  = blk / NTB;             // b*NCLS + c
    int t   = blk % NTB;
    int b   = bc / NCLS_;
    int c   = bc % NCLS_;
    int y0  = t * TILE_Y;
    int x   = threadIdx.x;           // 0..319

    const float* base = hmp + (size_t)bc * HW_;
    #pragma unroll
    for (int r = 0; r < TILE_Y+2; ++r) {
        int gy = y0 + r - 1;
        tile[r][x] = (gy >= 0 && gy < H_) ? __ldg(&base[gy*W_ + x]) : -3.0e38f;
    }
    shist[x] = 0;
    scur[x]  = 0;
    if (x == 0) lcnt = 0;
    __syncthreads();

    bool lf = (x > 0), rt = (x < W_-1);
    #pragma unroll
    for (int ly = 0; ly < TILE_Y; ++ly) {
        float raw = tile[ly+1][x];
        if (raw < RAW_PRE) continue;
        float m = fmaxf(tile[ly][x], tile[ly+2][x]);
        if (lf) m = fmaxf(m, fmaxf(tile[ly][x-1], fmaxf(tile[ly+1][x-1], tile[ly+2][x-1])));
        if (rt) m = fmaxf(m, fmaxf(tile[ly][x+1], fmaxf(tile[ly+1][x+1], tile[ly+2][x+1])));
        if (raw < m) {
            if (m - raw >= MARGIN_ && raw < 8.0f) continue;   // safe raw-space reject
            if (sigf(m) > sigf(raw)) continue;                // exact sigmoid-space tie check
        }
        float s = sigf(raw);                                  // exact reference sigmoid
        if (!(s >= THRESH_)) continue;
        int ind = (y0 + ly)*W_ + x;
        unsigned lo = 0xFFFFFFFFu - (unsigned)(c*HW_ + ind);
        unsigned long long key = ((unsigned long long)__float_as_uint(s) << 32) | lo;
        int p = atomicAdd(&lcnt, 1);
        if (p < LBUF_) {
            lbuf[p] = key;
            atomicAdd(&shist[key_bin(key)], 1);
        } else {  // rare overflow: immediate per-item reservation (merges correctly)
            int bin = key_bin(key);
            int gp  = atomicAdd(&g_hist[b][bin], 1);
            if (gp < BIN_CAP) g_cand2[b][bin][gp] = key;
        }
    }
    __syncthreads();
    int n = min(lcnt, LBUF_);
    // reserve per-bin global ranges (320 distinct addresses -> parallel atomics)
    {
        int cnt = shist[x];
        gpos[x] = cnt ? atomicAdd(&g_hist[b][x], cnt) : 0;
    }
    __syncthreads();
    // rebin pass: strided over lbuf, scatter into bucketed store
    for (int j = x; j < n; j += W_) {
        unsigned long long key = lbuf[j];
        int bin = key_bin(key);
        int loc = atomicAdd(&scur[bin], 1);
        int dst = gpos[bin] + loc;
        if (dst < BIN_CAP) g_cand2[b][bin][dst] = key;
    }
}

// ---------------- fused top-100 select + final math, one block per batch ----------------
__constant__ int c_chan[24] = {0,1,2,3,4,5,6,7,8,
                               26,28,30,32,34,36,38,40,42,44,
                               45,46,47,48,49};

__global__ void __launch_bounds__(NT_) k_selfin(
        const float* __restrict__ pred_reg,
        const float* __restrict__ calib,
        const float* __restrict__ pad_size,
        const float* __restrict__ dim_mean,
        float* __restrict__ out) {
    const int b    = blockIdx.x;
    const int tid  = threadIdx.x;            // 0..511 (thread == bin)
    const int lane = tid & 31, w = tid >> 5;
    __shared__ int S[NT_];
    __shared__ int wtot[16];
    __shared__ unsigned long long surv[SURV_];
    __shared__ unsigned long long sorted[K_];
    __shared__ float gv[K_][24];
    __shared__ int s_bstar;

    // capture clamped count, barrier, then reset (no read/write race)
    int hv = min(g_hist[b][tid], BIN_CAP);
    __syncthreads();
    g_hist[b][tid] = 0;

    // warp-shuffle suffix scan over 512 bins
    int val = hv;
    #pragma unroll
    for (int off = 1; off < 32; off <<= 1) {
        int tv = __shfl_down_sync(0xFFFFFFFFu, val, off);
        if (lane + off < 32) val += tv;
    }
    if (lane == 0) wtot[w] = val;
    __syncthreads();
    if (w == 0) {
        int tv = (lane < 16) ? wtot[lane] : 0;
        #pragma unroll
        for (int off = 1; off < 16; off <<= 1) {
            int t2 = __shfl_down_sync(0xFFFFFFFFu, tv, off);
            if (lane + off < 16) tv += t2;
        }
        if (lane < 16) wtot[lane] = tv;
    }
    __syncthreads();
    S[tid] = val + ((w + 1 < 16) ? wtot[w + 1] : 0);
    __syncthreads();

    int n = S[0];
    int target = n < K_ ? n : K_;

    if (target > 0) {
        {
            int nxt = (tid < NT_-1) ? S[tid + 1] : 0;
            if (S[tid] >= target && nxt < target) s_bstar = tid;
        }
        __syncthreads();
        const int bstar = s_bstar;
        // sc = S[bstar] <= S[bstar+1] + BIN_CAP < K_ + BIN_CAP <= SURV_  (provable)
        const int sc = min(S[bstar], SURV_);

        // copy only bins >= bstar (tiny: <= 612 keys total)
        if (tid >= bstar && tid < NBIN_ && hv > 0) {
            int dst = S[bstar] - S[tid];     // items in bins (tid, NBIN) placed before
            #pragma unroll 4
            for (int j = 0; j < hv; ++j) {
                int p = dst + j;
                if (p < SURV_) surv[p] = g_cand2[b][tid][j];
            }
        }
        __syncthreads();

        // rank-by-counting (keys unique): exact descending reference order
        for (int i = tid; i < sc; i += NT_) {
            unsigned long long ki = surv[i];
            int r = 0;
            for (int j = 0; j < sc; ++j) r += (surv[j] > ki);
            if (r < K_) sorted[r] = ki;
        }
        __syncthreads();

        // gather 24 channels per selected detection (latency-parallel)
        const float* rbase = pred_reg + (size_t)b * CREG_ * HW_;
        for (int i = tid; i < target * 24; i += NT_) {
            int d  = i / 24;
            int ch = i % 24;
            unsigned lo = 0xFFFFFFFFu - (unsigned)(sorted[d] & 0xFFFFFFFFu);
            int ind = (int)(lo % HW_);
            gv[d][ch] = __ldg(&rbase[c_chan[ch] * HW_ + ind]);
        }
        __syncthreads();
    }

    if (tid >= K_) return;
    float* row = out + (size_t)(b*K_ + tid) * NOUT_;
    if (tid >= target) {
        #pragma unroll
        for (int j = 0; j < NOUT_; ++j) row[j] = 0.0f;
        return;
    }

    unsigned long long key = sorted[tid];
    float score = __uint_as_float((unsigned)(key >> 32));
    unsigned lo = 0xFFFFFFFFu - (unsigned)(key & 0xFFFFFFFFu);
    int cls = (int)(lo / HW_);
    int ind = (int)(lo % HW_);
    float fx = (float)(ind % W_);
    float fy = (float)(ind / W_);
    const float* v = gv[tid];

    float fu = calib[b*4+0], cu = calib[b*4+1], fv = calib[b*4+2], cv = calib[b*4+3];
    float pw = pad_size[b*2+0], ph = pad_size[b*2+1];

    float r0 = fmaxf(v[0], 0.f), r1 = fmaxf(v[1], 0.f);
    float r2 = fmaxf(v[2], 0.f), r3 = fmaxf(v[3], 0.f);
    const float HIX = (float)(W_*4 - 1), HIY = (float)(H_*4 - 1);
    float bx0 = fminf(fmaxf((fx - r0)*4.f - pw, 0.f), HIX);
    float by0 = fminf(fmaxf((fy - r1)*4.f - ph, 0.f), HIY);
    float bx1 = fminf(fmaxf((fx + r2)*4.f - pw, 0.f), HIX);
    float by1 = fminf(fmaxf((fy + r3)*4.f - ph, 0.f), HIY);

    const float* dm = dim_mean + cls*3;
    float d0 = expf(v[6]) * dm[0];
    float d1 = expf(v[7]) * dm[1];
    float d2 = expf(v[8]) * dm[2];
    float h3d = d1;

    float fh = fu * h3d;
    float d_ctr = fh / (fmaxf(v[17] - v[18], 0.f)*4.f + EPS_);
    float d_02  = 0.5f * (fh / (fmaxf(v[9]  - v[13], 0.f)*4.f + EPS_)
                        + fh / (fmaxf(v[11] - v[15], 0.f)*4.f + EPS_));
    float d_13  = 0.5f * (fh / (fmaxf(v[10] - v[14], 0.f)*4.f + EPS_)
                        + fh / (fmaxf(v[12] - v[16], 0.f)*4.f + EPS_));
    float kd0 = fminf(fmaxf(d_ctr, 0.1f), 100.f);
    float kd1 = fminf(fmaxf(d_02 , 0.1f), 100.f);
    float kd2 = fminf(fmaxf(d_13 , 0.1f), 100.f);

    float doff   = v[22];
    float sgd    = 1.0f / (1.0f + expf(-doff));
    float direct = fminf(fmaxf(1.0f / sgd - 1.0f, 0.1f), 100.f);

    float u0 = expf(v[23]);
    float u1 = expf(v[19]);
    float u2 = expf(v[20]);
    float u3 = expf(v[21]);
    float w0 = 1.f/u0, w1 = 1.f/u1, w2 = 1.f/u2, w3 = 1.f/u3;
    float Sw = w0 + w1 + w2 + w3;
    w0 /= Sw; w1 /= Sw; w2 /= Sw; w3 /= Sw;
    float depth = direct*w0 + kd0*w1 + kd1*w2 + kd2*w3;
    float derr  = w0*u0 + w1*u1 + w2*u2 + w3*u3;

    float projx = (fx + v[4])*4.f - pw;
    float projy = (fy + v[5])*4.f - ph;
    float x3 = (projx - cu) * depth / fu;
    float y3 = (projy - cv) * depth / fv;

    row[0]  = (float)cls;
    row[1]  = score;
    row[2]  = bx0;  row[3]  = by0;  row[4]  = bx1;  row[5]  = by1;
    row[6]  = d0;   row[7]  = d1;   row[8]  = d2;
    row[9]  = x3;   row[10] = y3;   row[11] = depth;
    row[12] = derr;
}

extern "C" void kernel_launch(void* const* d_in, const int* in_sizes, int n_in,
                              void* d_out, int out_size) {
    const float* pred_hmp = (const float*)d_in[0];
    const float* pred_reg = (const float*)d_in[1];
    const float* calib    = (const float*)d_in[2];
    const float* pad_size = (const float*)d_in[3];
    const float* dim_mean = (const float*)d_in[4];
    float* out = (float*)d_out;

    k_nms<<<B_*NCLS_*NTB, W_>>>(pred_hmp);
    k_selfin<<<B_, NT_>>>(pred_reg, calib, pad_size, dim_mean, out);
}